// round 4
// baseline (speedup 1.0000x reference)
#include <cuda_runtime.h>
#include <math.h>

#define Bsz 4
#define Ssz 8192
#define Dsz 1024
#define Nsz 12
#define NROWS (Bsz*Ssz)
#define NCHUNK 32           // s-chunks per batch element
#define CHUNK 256           // rows per chunk (NCHUNK*CHUNK = Ssz)
#define RB 8                // row batch in K1
#define K2_BLOCKS 128

// Scratch (allocation-free rule: __device__ globals)
__device__ float g_w[NROWS * Nsz];
__device__ float g_Upart[NCHUNK * Bsz * Nsz * Dsz];   // 6.3 MB
__device__ float g_U[Bsz * Nsz * Dsz];
__device__ float g_SV[Bsz * Nsz * Dsz];
__device__ float g_T[Bsz * Nsz * Dsz];
__device__ unsigned g_barcnt[4];                       // zero-init; monotonic

// ---- packed f32x2 helpers -------------------------------------------------
__device__ __forceinline__ void ffma2(unsigned long long& d,
                                      unsigned long long a,
                                      unsigned long long b) {
    asm("fma.rn.f32x2 %0, %1, %2, %0;" : "+l"(d) : "l"(a), "l"(b));
}
__device__ __forceinline__ float2 u2f(unsigned long long v) {
    float2 f;
    asm("mov.b64 {%0,%1}, %2;" : "=f"(f.x), "=f"(f.y) : "l"(v));
    return f;
}
__device__ __forceinline__ unsigned long long f2u(float lo, float hi) {
    unsigned long long v;
    asm("mov.b64 %0, {%1,%2};" : "=l"(v) : "f"(lo), "f"(hi));
    return v;
}

// ---------------------------------------------------------------------------
// K1: fused splat-weight + U-partial kernel.
// Grid (NCHUNK, Bsz) = 128 blocks, 256 threads. Thread owns d-cols [4t,4t+4).
// ---------------------------------------------------------------------------
__global__ void __launch_bounds__(256, 1)
k1_fused(const float* __restrict__ x, const float* __restrict__ centers,
         const float* __restrict__ scales, const float* __restrict__ amps) {
    __shared__ unsigned long long part2[RB][13][32];   // packed partials, 26.6 KB
    __shared__ float red[RB][13];
    __shared__ unsigned long long wsm2[RB][Nsz];       // w duplicated into both lanes
    __shared__ float c2part[8][Nsz];
    __shared__ float c2s[Nsz], invs[Nsz], ampv[Nsz];

    const int t = threadIdx.x, warp = t >> 5, lane = t & 31;
    const int sc = blockIdx.x, b = blockIdx.y;
    const size_t row0 = (size_t)b * Ssz + (size_t)sc * CHUNK;

    // centers for this thread's 4 columns, packed (2x f32x2 each)
    ulonglong2 cfp[Nsz];
    #pragma unroll
    for (int n = 0; n < Nsz; n++)
        cfp[n] = *(const ulonglong2*)(centers + n * Dsz + t * 4);

    // per-block param computation: c2[n], 0.5/sigma^2, sigmoid(amp)
    {
        #pragma unroll
        for (int n = 0; n < Nsz; n++) {
            float2 a = u2f(cfp[n].x), c = u2f(cfp[n].y);
            float p = a.x * a.x + a.y * a.y + c.x * c.x + c.y * c.y;
            #pragma unroll
            for (int o = 16; o > 0; o >>= 1)
                p += __shfl_down_sync(0xffffffffu, p, o);
            if (lane == 0) c2part[warp][n] = p;
        }
        __syncthreads();
        if (t < Nsz) {
            float s = 0.f;
            #pragma unroll
            for (int w = 0; w < 8; w++) s += c2part[w][t];
            c2s[t] = s;
            float sv = expf(scales[t]);
            sv = fminf(fmaxf(sv, 0.1f), 2.0f);
            invs[t] = 0.5f / (sv * sv);
            ampv[t] = 1.f / (1.f + expf(-amps[t]));
        }
        __syncthreads();
    }

    // accumulators for U over this chunk (12 x float4, packed)
    ulonglong2 acc[Nsz];
    #pragma unroll
    for (int n = 0; n < Nsz; n++) { acc[n].x = 0ull; acc[n].y = 0ull; }

    const ulonglong2* xp = (const ulonglong2*)(x + row0 * Dsz) + t;
    ulonglong2 xbuf[2][RB];
    #pragma unroll
    for (int r = 0; r < RB; r++) xbuf[0][r] = xp[(size_t)r * (Dsz / 4)];

    const int NSB = CHUNK / RB;  // 32 sub-batches
    for (int sb = 0; sb < NSB; sb++) {
        const int cur = sb & 1;
        if (sb < NSB - 1) {
            #pragma unroll
            for (int r = 0; r < RB; r++)
                xbuf[cur ^ 1][r] = xp[(size_t)((sb + 1) * RB + r) * (Dsz / 4)];
        }
        // dots: 13 packed partials per row, dumped packed to smem
        #pragma unroll
        for (int r = 0; r < RB; r++) {
            unsigned long long p2[13];
            #pragma unroll
            for (int i = 0; i < 13; i++) p2[i] = 0ull;
            ulonglong2 xv = xbuf[cur][r];
            #pragma unroll
            for (int n = 0; n < Nsz; n++) {
                ffma2(p2[n], xv.x, cfp[n].x);
                ffma2(p2[n], xv.y, cfp[n].y);
            }
            ffma2(p2[12], xv.x, xv.x);
            ffma2(p2[12], xv.y, xv.y);
            #pragma unroll
            for (int i = 0; i < 13; i++) part2[r][i][lane + 0] = (warp & 1) ? 0ull : p2[i];
            // NOTE: above would clobber; replaced by per-warp slot below
        }
        // (the loop above is logically replaced; real store happens here)
        __syncthreads();
        __syncthreads();
        (void)0;
        break;  // placeholder never reached (restructured below)
    }
    // ---- real implementation continues in k1_fused_impl (see below) ----
}

// NOTE: k1_fused above had a structural flaw in the smem dump (32 slots vs
// 256 threads). The real K1 used is k1_fused2: partials are REDUCED 8:1 by
// lane-folding inside the warp via packed adds before the dump.
__device__ __forceinline__ void addf2(unsigned long long& d, unsigned long long a) {
    asm("add.rn.f32x2 %0, %0, %1;" : "+l"(d) : "l"(a));
}
__device__ __forceinline__ unsigned long long shfl_u64(unsigned long long v, int off) {
    float2 f = u2f(v);
    f.x += __shfl_down_sync(0xffffffffu, f.x, off);
    f.y += __shfl_down_sync(0xffffffffu, f.y, off);
    return f2u(f.x, f.y);
}

__global__ void __launch_bounds__(256, 1)
k1_fused2(const float* __restrict__ x, const float* __restrict__ centers,
          const float* __restrict__ scales, const float* __restrict__ amps) {
    __shared__ unsigned long long part2[RB][13][32];   // [row][val][8warps*4lanes]
    __shared__ float red[RB][13];
    __shared__ unsigned long long wsm2[RB][Nsz];
    __shared__ float c2part[8][Nsz];
    __shared__ float c2s[Nsz], invs[Nsz], ampv[Nsz];

    const int t = threadIdx.x, warp = t >> 5, lane = t & 31;
    const int sc = blockIdx.x, b = blockIdx.y;
    const size_t row0 = (size_t)b * Ssz + (size_t)sc * CHUNK;

    ulonglong2 cfp[Nsz];
    #pragma unroll
    for (int n = 0; n < Nsz; n++)
        cfp[n] = *(const ulonglong2*)(centers + n * Dsz + t * 4);

    #pragma unroll
    for (int n = 0; n < Nsz; n++) {
        float2 a = u2f(cfp[n].x), c = u2f(cfp[n].y);
        float p = a.x * a.x + a.y * a.y + c.x * c.x + c.y * c.y;
        #pragma unroll
        for (int o = 16; o > 0; o >>= 1)
            p += __shfl_down_sync(0xffffffffu, p, o);
        if (lane == 0) c2part[warp][n] = p;
    }
    __syncthreads();
    if (t < Nsz) {
        float s = 0.f;
        #pragma unroll
        for (int w = 0; w < 8; w++) s += c2part[w][t];
        c2s[t] = s;
        float sv = expf(scales[t]);
        sv = fminf(fmaxf(sv, 0.1f), 2.0f);
        invs[t] = 0.5f / (sv * sv);
        ampv[t] = 1.f / (1.f + expf(-amps[t]));
    }
    __syncthreads();

    ulonglong2 acc[Nsz];
    #pragma unroll
    for (int n = 0; n < Nsz; n++) { acc[n].x = 0ull; acc[n].y = 0ull; }

    const ulonglong2* xp = (const ulonglong2*)(x + row0 * Dsz) + t;
    ulonglong2 xbuf[2][RB];
    #pragma unroll
    for (int r = 0; r < RB; r++) xbuf[0][r] = xp[(size_t)r * (Dsz / 4)];

    const int NSB = CHUNK / RB;
    for (int sb = 0; sb < NSB; sb++) {
        const int cur = sb & 1;
        if (sb < NSB - 1) {
            #pragma unroll
            for (int r = 0; r < RB; r++)
                xbuf[cur ^ 1][r] = xp[(size_t)((sb + 1) * RB + r) * (Dsz / 4)];
        }
        #pragma unroll
        for (int r = 0; r < RB; r++) {
            unsigned long long p2[13];
            #pragma unroll
            for (int i = 0; i < 13; i++) p2[i] = 0ull;
            ulonglong2 xv = xbuf[cur][r];
            #pragma unroll
            for (int n = 0; n < Nsz; n++) {
                ffma2(p2[n], xv.x, cfp[n].x);
                ffma2(p2[n], xv.y, cfp[n].y);
            }
            ffma2(p2[12], xv.x, xv.x);
            ffma2(p2[12], xv.y, xv.y);
            // fold 32 lanes -> 4 lanes (3 packed-shfl stages), dump packed
            #pragma unroll
            for (int i = 0; i < 13; i++) {
                unsigned long long v = p2[i];
                v = shfl_u64(v, 16);
                v = shfl_u64(v, 8);
                v = shfl_u64(v, 4);
                if (lane < 4) part2[r][i][warp * 4 + lane] = v;
            }
        }
        __syncthreads();
        // reduce 32 packed slots (=64 floats) per (row,val)
        if (t < RB * 13) {
            int r = t / 13, i = t - r * 13;
            const float4* q = (const float4*)&part2[r][i][0];
            float4 s = q[0];
            #pragma unroll
            for (int j = 1; j < 16; j++) {
                float4 v = q[j];
                s.x += v.x; s.y += v.y; s.z += v.z; s.w += v.w;
            }
            red[r][i] = (s.x + s.y) + (s.z + s.w);
        }
        __syncthreads();
        // per-row softmax-like weight finalize
        if (t < RB) {
            float x2 = red[t][12];
            float g[Nsz], sum = 0.f;
            #pragma unroll
            for (int n = 0; n < Nsz; n++) {
                float d2 = fmaxf(x2 + c2s[n] - 2.f * red[t][n], 0.f);
                g[n] = __expf(-d2 * invs[n]) * ampv[n];
                sum += g[n];
            }
            float inv = 1.f / fmaxf(sum, 1e-8f);
            #pragma unroll
            for (int n = 0; n < Nsz; n++) {
                float wv = g[n] * inv;
                wsm2[t][n] = f2u(wv, wv);
            }
        }
        __syncthreads();
        // write w to gmem (coalesced-ish, 96 floats)
        if (t < RB * Nsz) {
            int r = t / Nsz, n = t - r * Nsz;
            g_w[(row0 + sb * RB + r) * Nsz + n] = u2f(wsm2[r][n]).x;
        }
        // accumulate U partials from registers
        #pragma unroll
        for (int r = 0; r < RB; r++) {
            ulonglong2 xv = xbuf[cur][r];
            #pragma unroll
            for (int n = 0; n < Nsz; n++) {
                unsigned long long wp = wsm2[r][n];
                ffma2(acc[n].x, wp, xv.x);
                ffma2(acc[n].y, wp, xv.y);
            }
        }
        __syncthreads();
    }
    // flush partials
    #pragma unroll
    for (int n = 0; n < Nsz; n++) {
        size_t idx = ((size_t)(sc * Bsz + b) * Nsz + n) * Dsz + t * 4;
        *(ulonglong2*)(g_Upart + idx) = acc[n];
    }
}

// ---------------------------------------------------------------------------
// K2: monolithic tail. 128 blocks x 256 thr, hand-rolled replay-safe grid bar.
// ---------------------------------------------------------------------------
__device__ __forceinline__ void gridbar(int k, unsigned nb) {
    __syncthreads();
    __threadfence();
    if (threadIdx.x == 0) {
        unsigned pos = atomicAdd(&g_barcnt[k], 1u);
        unsigned target = (pos / nb + 1u) * nb;
        unsigned v;
        do {
            asm volatile("ld.acquire.gpu.u32 %0, [%1];" : "=r"(v) : "l"(&g_barcnt[k]));
        } while (v < target);
    }
    __syncthreads();
}

__global__ void __launch_bounds__(256, 1)
k2_tail(const float* __restrict__ w_value, const float* __restrict__ w_output,
        float* __restrict__ out) {
    __shared__ float As[64][49];
    __shared__ float Ws[64][66];

    const int t = threadIdx.x;
    const unsigned gtid = blockIdx.x * 256 + t;

    // ---- phase 0: reduce Upart -> U; zero SV, T ----
    if (gtid < (Bsz * Nsz * Dsz) / 4) {
        int d4 = gtid & 255;
        int bn = gtid >> 8;
        float4 s = make_float4(0.f, 0.f, 0.f, 0.f);
        #pragma unroll 8
        for (int sc = 0; sc < NCHUNK; sc++) {
            float4 v = *(const float4*)(g_Upart + (((size_t)sc * 48 + bn) << 10) + d4 * 4);
            s.x += v.x; s.y += v.y; s.z += v.z; s.w += v.w;
        }
        *(float4*)(g_U + (((size_t)bn) << 10) + d4 * 4) = s;
        float4 z = make_float4(0.f, 0.f, 0.f, 0.f);
        *(float4*)(g_SV + (((size_t)bn) << 10) + d4 * 4) = z;
        *(float4*)(g_T + (((size_t)bn) << 10) + d4 * 4) = z;
    }
    gridbar(0, K2_BLOCKS);

    // ---- phases 1,2: K-split gemms (48 x 1024 x 1024 each) ----
    for (int phase = 0; phase < 2; phase++) {
        const float* A = phase ? g_SV : g_U;
        const float* W = phase ? w_output : w_value;
        float* C = phase ? g_T : g_SV;
        for (int tile = blockIdx.x; tile < 256; tile += K2_BLOCKS) {
            int e0 = (tile & 15) * 64;
            int k0 = (tile >> 4) * 64;
            __syncthreads();
            for (int idx = t; idx < 48 * 64; idx += 256) {
                int m = idx >> 6, kk = idx & 63;
                As[kk][m] = A[(size_t)m * Dsz + k0 + kk];
            }
            for (int idx = t; idx < 64 * 64; idx += 256) {
                int e = idx >> 6, kk = idx & 63;
                Ws[kk][e] = W[(size_t)(e0 + e) * Dsz + k0 + kk];
            }
            __syncthreads();
            int ty = t >> 5, tx = t & 31;
            float a0[6][2];
            #pragma unroll
            for (int i = 0; i < 6; i++) { a0[i][0] = 0.f; a0[i][1] = 0.f; }
            for (int kk = 0; kk < 64; kk++) {
                float av[6];
                #pragma unroll
                for (int i = 0; i < 6; i++) av[i] = As[kk][ty * 6 + i];
                float2 wv = *(const float2*)&Ws[kk][tx * 2];
                #pragma unroll
                for (int i = 0; i < 6; i++) {
                    a0[i][0] += av[i] * wv.x;
                    a0[i][1] += av[i] * wv.y;
                }
            }
            #pragma unroll
            for (int i = 0; i < 6; i++) {
                int m = ty * 6 + i;
                atomicAdd(&C[(size_t)m * Dsz + e0 + tx * 2 + 0], a0[i][0]);
                atomicAdd(&C[(size_t)m * Dsz + e0 + tx * 2 + 1], a0[i][1]);
            }
        }
        gridbar(1 + phase, K2_BLOCKS);
    }

    // ---- phase 3: expand. T[b] in registers (12 x float4 per thread) ----
    {
        int b = blockIdx.x >> 5;          // 0..3
        int chunk = blockIdx.x & 31;      // 0..31
        size_t row0 = (size_t)b * Ssz + (size_t)chunk * 256;

        ulonglong2 trp[Nsz];
        #pragma unroll
        for (int n = 0; n < Nsz; n++)
            trp[n] = *(const ulonglong2*)(g_T + ((size_t)(b * Nsz + n)) * Dsz + t * 4);

        for (int r = 0; r < 256; r++) {
            size_t row = row0 + r;
            const float4* wr = (const float4*)(g_w + row * Nsz);
            float4 w0 = __ldg(&wr[0]);
            float4 w1 = __ldg(&wr[1]);
            float4 w2 = __ldg(&wr[2]);
            float wf[Nsz] = {w0.x, w0.y, w0.z, w0.w, w1.x, w1.y, w1.z, w1.w,
                             w2.x, w2.y, w2.z, w2.w};
            ulonglong2 o;
            o.x = 0ull; o.y = 0ull;
            #pragma unroll
            for (int n = 0; n < Nsz; n++) {
                unsigned long long wp = f2u(wf[n], wf[n]);
                ffma2(o.x, wp, trp[n].x);
                ffma2(o.y, wp, trp[n].y);
            }
            *(ulonglong2*)(out + row * Dsz + t * 4) = o;
        }
    }
}

extern "C" void kernel_launch(void* const* d_in, const int* in_sizes, int n_in,
                              void* d_out, int out_size) {
    const float* x        = (const float*)d_in[0];
    const float* centers  = (const float*)d_in[1];
    const float* scales   = (const float*)d_in[2];
    const float* amps     = (const float*)d_in[3];
    const float* w_value  = (const float*)d_in[4];
    const float* w_output = (const float*)d_in[5];
    float* out = (float*)d_out;

    k1_fused2<<<dim3(NCHUNK, Bsz), 256>>>(x, centers, scales, amps);
    k2_tail<<<K2_BLOCKS, 256>>>(w_value, w_output, out);
}

// round 5
// speedup vs baseline: 1.4961x; 1.4961x over previous
#include <cuda_runtime.h>
#include <math.h>

#define Bsz 4
#define Ssz 8192
#define Dsz 1024
#define Nsz 12
#define NROWS (Bsz*Ssz)
#define CH 64                 // rows per K1 block
#define NCH (Ssz/CH)          // 128 chunks per batch
#define K2_BLOCKS 128

typedef unsigned long long u64;

// Scratch (allocation-free rule: __device__ globals)
__device__ u64   g_wdup[NROWS * Nsz];                 // w duplicated (lo=hi) 3MB
__device__ float g_Upart[NCH * Bsz * Nsz * Dsz];      // 25.2 MB partials
__device__ float g_U[Bsz * Nsz * Dsz];
__device__ float g_SV[Bsz * Nsz * Dsz];
__device__ float g_T[Bsz * Nsz * Dsz];
__device__ unsigned g_barcnt[4];                      // zero-init; monotonic

// ---- packed f32x2 helpers -------------------------------------------------
__device__ __forceinline__ void ffma2(u64& d, u64 a, u64 b) {
    asm("fma.rn.f32x2 %0, %1, %2, %0;" : "+l"(d) : "l"(a), "l"(b));
}
__device__ __forceinline__ float2 u2f(u64 v) {
    float2 f;
    asm("mov.b64 {%0,%1}, %2;" : "=f"(f.x), "=f"(f.y) : "l"(v));
    return f;
}
__device__ __forceinline__ u64 f2u(float lo, float hi) {
    u64 v;
    asm("mov.b64 %0, {%1,%2};" : "=l"(v) : "f"(lo), "f"(hi));
    return v;
}

// ---------------------------------------------------------------------------
// K1: fused splat-weights + U-partials.
// Grid (NCH, Bsz) = 512 blocks, 256 threads.
// W-phase: 128 threads per row (k-slice 8), 2 rows concurrently per block.
// Accum-phase: k-slice 4 over full D, x re-read (L2-resident).
// ---------------------------------------------------------------------------
__global__ void __launch_bounds__(256, 1)
k1_fused(const float* __restrict__ x, const float* __restrict__ centers,
         const float* __restrict__ scales, const float* __restrict__ amps) {
    __shared__ float part[2][4][13][32];    // [slot][j][val][4warps*8lanes] 13.3KB
    __shared__ float red[2][4][13];
    __shared__ u64   wdup_s[CH][Nsz];       // 6KB
    __shared__ float c2part[4][Nsz];
    __shared__ float c2s[Nsz], invs[Nsz], ampv[Nsz];

    const int t = threadIdx.x, lane = t & 31;
    const int slot = t >> 7;                // 0..1 (row slot)
    const int st = t & 127;                 // thread-in-slot
    const int sw = (t >> 5) & 3;            // warp-in-slot
    const int chunk = blockIdx.x, b = blockIdx.y;
    const size_t row0 = (size_t)b * Ssz + (size_t)chunk * CH;

    // centers for this thread's 8 columns (k-slice 8), packed u64 pairs
    ulonglong2 cA[Nsz], cB[Nsz];
    #pragma unroll
    for (int n = 0; n < Nsz; n++) {
        cA[n] = *(const ulonglong2*)(centers + n * Dsz + st * 8);
        cB[n] = *(const ulonglong2*)(centers + n * Dsz + st * 8 + 4);
    }

    // per-block params: c2 (from slot-0 warps only), sigma, amp
    if (slot == 0) {
        #pragma unroll
        for (int n = 0; n < Nsz; n++) {
            float2 a0 = u2f(cA[n].x), a1 = u2f(cA[n].y);
            float2 b0 = u2f(cB[n].x), b1 = u2f(cB[n].y);
            float p = a0.x*a0.x + a0.y*a0.y + a1.x*a1.x + a1.y*a1.y
                    + b0.x*b0.x + b0.y*b0.y + b1.x*b1.x + b1.y*b1.y;
            #pragma unroll
            for (int o = 16; o > 0; o >>= 1)
                p += __shfl_down_sync(0xffffffffu, p, o);
            if (lane == 0) c2part[sw][n] = p;
        }
    }
    __syncthreads();
    if (t < Nsz) {
        c2s[t] = c2part[0][t] + c2part[1][t] + c2part[2][t] + c2part[3][t];
        float sv = expf(scales[t]);
        sv = fminf(fmaxf(sv, 0.1f), 2.0f);
        invs[t] = 0.5f / (sv * sv);
        ampv[t] = 1.f / (1.f + expf(-amps[t]));
    }
    __syncthreads();

    // ---------------- W-PHASE: 8 batches x 8 rows --------------------------
    for (int bat = 0; bat < CH / 8; bat++) {
        // load 4 rows for this slot (8 LDG.128, batched for MLP)
        ulonglong2 xA[4], xB[4];
        #pragma unroll
        for (int j = 0; j < 4; j++) {
            const float* xr = x + (row0 + bat * 8 + slot * 4 + j) * Dsz + st * 8;
            xA[j] = *(const ulonglong2*)xr;
            xB[j] = *(const ulonglong2*)(xr + 4);
        }
        #pragma unroll
        for (int j = 0; j < 4; j++) {
            u64 p2[13];
            #pragma unroll
            for (int i = 0; i < 13; i++) p2[i] = 0ull;
            #pragma unroll
            for (int n = 0; n < Nsz; n++) {
                ffma2(p2[n], xA[j].x, cA[n].x);
                ffma2(p2[n], xA[j].y, cA[n].y);
                ffma2(p2[n], xB[j].x, cB[n].x);
                ffma2(p2[n], xB[j].y, cB[n].y);
            }
            ffma2(p2[12], xA[j].x, xA[j].x);
            ffma2(p2[12], xA[j].y, xA[j].y);
            ffma2(p2[12], xB[j].x, xB[j].x);
            ffma2(p2[12], xB[j].y, xB[j].y);
            // collapse pairs, then 2-stage xor fold (lanes 0..7 hold orbit sums)
            float p[13];
            #pragma unroll
            for (int i = 0; i < 13; i++) {
                float2 f = u2f(p2[i]);
                p[i] = f.x + f.y;
            }
            #pragma unroll
            for (int i = 0; i < 13; i++) {
                p[i] += __shfl_xor_sync(0xffffffffu, p[i], 16);
                p[i] += __shfl_xor_sync(0xffffffffu, p[i], 8);
            }
            if (lane < 8) {
                #pragma unroll
                for (int i = 0; i < 13; i++)
                    part[slot][j][i][sw * 8 + lane] = p[i];
            }
        }
        __syncthreads();
        // reduce 32 slots per (slot,row,val): 104 items
        if (t < 104) {
            int s = t / 52, rem = t % 52, j = rem / 13, i = rem % 13;
            const float4* q = (const float4*)part[s][j][i];
            float4 v0 = q[0], v1 = q[1], v2 = q[2], v3 = q[3];
            float4 v4 = q[4], v5 = q[5], v6 = q[6], v7 = q[7];
            float s0 = (v0.x+v0.y+v0.z+v0.w) + (v1.x+v1.y+v1.z+v1.w);
            float s1 = (v2.x+v2.y+v2.z+v2.w) + (v3.x+v3.y+v3.z+v3.w);
            float s2 = (v4.x+v4.y+v4.z+v4.w) + (v5.x+v5.y+v5.z+v5.w);
            float s3 = (v6.x+v6.y+v6.z+v6.w) + (v7.x+v7.y+v7.z+v7.w);
            red[s][j][i] = (s0 + s1) + (s2 + s3);
        }
        __syncthreads();
        // finalize 8 rows
        if (t < 8) {
            int s = t >> 2, j = t & 3;
            int rloc = bat * 8 + t;
            float x2 = red[s][j][12];
            float g[Nsz], sum = 0.f;
            #pragma unroll
            for (int n = 0; n < Nsz; n++) {
                float d2 = fmaxf(x2 + c2s[n] - 2.f * red[s][j][n], 0.f);
                g[n] = __expf(-d2 * invs[n]) * ampv[n];
                sum += g[n];
            }
            float inv = 1.f / fmaxf(sum, 1e-8f);
            #pragma unroll
            for (int n = 0; n < Nsz; n++) {
                u64 wd = f2u(g[n] * inv, g[n] * inv);
                wdup_s[rloc][n] = wd;
                g_wdup[(row0 + rloc) * Nsz + n] = wd;
            }
        }
        __syncthreads();
    }

    // ---------------- ACCUM PHASE: k-slice 4, x re-read (L2-hot) -----------
    ulonglong2 acc[Nsz];
    #pragma unroll
    for (int n = 0; n < Nsz; n++) { acc[n].x = 0ull; acc[n].y = 0ull; }

    for (int rb = 0; rb < CH; rb += 8) {
        ulonglong2 xv[8];
        #pragma unroll
        for (int r = 0; r < 8; r++)
            xv[r] = *(const ulonglong2*)(x + (row0 + rb + r) * Dsz + t * 4);
        #pragma unroll
        for (int r = 0; r < 8; r++) {
            const ulonglong2* wp = (const ulonglong2*)wdup_s[rb + r];
            #pragma unroll
            for (int p = 0; p < 6; p++) {
                ulonglong2 q = wp[p];
                ffma2(acc[2*p  ].x, q.x, xv[r].x);
                ffma2(acc[2*p  ].y, q.x, xv[r].y);
                ffma2(acc[2*p+1].x, q.y, xv[r].x);
                ffma2(acc[2*p+1].y, q.y, xv[r].y);
            }
        }
    }
    #pragma unroll
    for (int n = 0; n < Nsz; n++) {
        size_t idx = (((size_t)chunk * Bsz + b) * Nsz + n) * Dsz + t * 4;
        *(ulonglong2*)(g_Upart + idx) = acc[n];
    }
}

// ---------------------------------------------------------------------------
// K2: monolithic tail. 128 blocks x 256 thr, replay-safe gridbars.
// ---------------------------------------------------------------------------
__device__ __forceinline__ void gridbar(int k, unsigned nb) {
    __syncthreads();
    __threadfence();
    if (threadIdx.x == 0) {
        unsigned pos = atomicAdd(&g_barcnt[k], 1u);
        unsigned target = (pos / nb + 1u) * nb;
        unsigned v;
        do {
            asm volatile("ld.acquire.gpu.u32 %0, [%1];" : "=r"(v) : "l"(&g_barcnt[k]));
        } while (v < target);
    }
    __syncthreads();
}

union SmemK2 {
    struct { float As[64][49]; float Ws[64][66]; } g;
    u64 wd[256][Nsz];
};

__global__ void __launch_bounds__(256, 1)
k2_tail(const float* __restrict__ w_value, const float* __restrict__ w_output,
        float* __restrict__ out) {
    __shared__ SmemK2 sm;
    const int t = threadIdx.x;
    const unsigned gtid = blockIdx.x * 256 + t;

    // ---- phase 0: reduce Upart -> U; zero SV, T ----
    if (gtid < (Bsz * Nsz * Dsz) / 4) {
        int d4 = gtid & 255;
        int bn = gtid >> 8;
        int b = bn / Nsz, n = bn % Nsz;
        float4 s = make_float4(0.f, 0.f, 0.f, 0.f);
        #pragma unroll 8
        for (int c = 0; c < NCH; c++) {
            float4 v = *(const float4*)(g_Upart +
                ((((size_t)c * Bsz + b) * Nsz + n) << 10) + d4 * 4);
            s.x += v.x; s.y += v.y; s.z += v.z; s.w += v.w;
        }
        *(float4*)(g_U + (((size_t)bn) << 10) + d4 * 4) = s;
        float4 z = make_float4(0.f, 0.f, 0.f, 0.f);
        *(float4*)(g_SV + (((size_t)bn) << 10) + d4 * 4) = z;
        *(float4*)(g_T + (((size_t)bn) << 10) + d4 * 4) = z;
    }
    gridbar(0, K2_BLOCKS);

    // ---- phases 1,2: K-split gemms (48 x 1024 x 1024) ----
    for (int phase = 0; phase < 2; phase++) {
        const float* A = phase ? g_SV : g_U;
        const float* W = phase ? w_output : w_value;
        float* C = phase ? g_T : g_SV;
        for (int tile = blockIdx.x; tile < 256; tile += K2_BLOCKS) {
            int e0 = (tile & 15) * 64;
            int k0 = (tile >> 4) * 64;
            __syncthreads();
            for (int idx = t; idx < 48 * 64; idx += 256) {
                int m = idx >> 6, kk = idx & 63;
                sm.g.As[kk][m] = A[(size_t)m * Dsz + k0 + kk];
            }
            for (int idx = t; idx < 64 * 64; idx += 256) {
                int e = idx >> 6, kk = idx & 63;
                sm.g.Ws[kk][e] = W[(size_t)(e0 + e) * Dsz + k0 + kk];
            }
            __syncthreads();
            int ty = t >> 5, tx = t & 31;
            float a0[6][2];
            #pragma unroll
            for (int i = 0; i < 6; i++) { a0[i][0] = 0.f; a0[i][1] = 0.f; }
            for (int kk = 0; kk < 64; kk++) {
                float av[6];
                #pragma unroll
                for (int i = 0; i < 6; i++) av[i] = sm.g.As[kk][ty * 6 + i];
                float2 wv = *(const float2*)&sm.g.Ws[kk][tx * 2];
                #pragma unroll
                for (int i = 0; i < 6; i++) {
                    a0[i][0] += av[i] * wv.x;
                    a0[i][1] += av[i] * wv.y;
                }
            }
            #pragma unroll
            for (int i = 0; i < 6; i++) {
                int m = ty * 6 + i;
                atomicAdd(&C[(size_t)m * Dsz + e0 + tx * 2 + 0], a0[i][0]);
                atomicAdd(&C[(size_t)m * Dsz + e0 + tx * 2 + 1], a0[i][1]);
            }
        }
        gridbar(1 + phase, K2_BLOCKS);
    }

    // ---- phase 3: expand. T in regs, wdup staged in smem ----
    {
        int b = blockIdx.x >> 5;          // 0..3
        int ch = blockIdx.x & 31;         // 0..31 (256 rows each)
        size_t row0 = (size_t)b * Ssz + (size_t)ch * 256;

        ulonglong2 trp[Nsz];
        #pragma unroll
        for (int n = 0; n < Nsz; n++)
            trp[n] = *(const ulonglong2*)(g_T + ((size_t)(b * Nsz + n)) * Dsz + t * 4);

        // stage duplicated w for 256 rows (24KB)
        for (int i = t; i < 256 * Nsz; i += 256)
            sm.wd[i / Nsz][i % Nsz] = g_wdup[(row0 + i / Nsz) * Nsz + i % Nsz];
        __syncthreads();

        for (int r = 0; r < 256; r++) {
            const ulonglong2* wp = (const ulonglong2*)sm.wd[r];
            u64 ox = 0ull, oy = 0ull;
            #pragma unroll
            for (int p = 0; p < 6; p++) {
                ulonglong2 q = wp[p];
                ffma2(ox, q.x, trp[2*p  ].x);
                ffma2(oy, q.x, trp[2*p  ].y);
                ffma2(ox, q.y, trp[2*p+1].x);
                ffma2(oy, q.y, trp[2*p+1].y);
            }
            ulonglong2 o; o.x = ox; o.y = oy;
            *(ulonglong2*)(out + (row0 + r) * Dsz + t * 4) = o;
        }
    }
}

extern "C" void kernel_launch(void* const* d_in, const int* in_sizes, int n_in,
                              void* d_out, int out_size) {
    const float* x        = (const float*)d_in[0];
    const float* centers  = (const float*)d_in[1];
    const float* scales   = (const float*)d_in[2];
    const float* amps     = (const float*)d_in[3];
    const float* w_value  = (const float*)d_in[4];
    const float* w_output = (const float*)d_in[5];
    float* out = (float*)d_out;

    k1_fused<<<dim3(NCH, Bsz), 256>>>(x, centers, scales, amps);
    k2_tail<<<K2_BLOCKS, 256>>>(w_value, w_output, out);
}